// round 4
// baseline (speedup 1.0000x reference)
#include <cuda_runtime.h>
#include <cstdint>

// Haar DWT level-1 on x: (8, 64, 512, 512) fp32 -> 4 quadrants (8,64,256,256)
// concatenated in d_out as [ll | lh | hl | hh].
//
// Persistent grid-stride version of the R2 shape: each tile is a 2x8 input
// patch (4x float4 streaming loads, MLP=4) -> four 2x2 Haar butterflies ->
// one float4 streaming store per quadrant. A fixed resident grid
// (148 SMs x 8 CTAs) loops over all 8,388,608 tiles, keeping the DRAM
// request stream continuous across tile boundaries (no CTA launch/drain gaps).

static constexpr unsigned NTILES = 8u * 1024u * 1024u;   // 512 planes * 256 rows * 64 col-groups
static constexpr unsigned NBLOCKS = 148u * 8u;           // persistent grid: 1184 CTAs
static constexpr unsigned NTHREADS = 256u;

__global__ __launch_bounds__(NTHREADS, 8)
void haar_dwt_kernel(const float* __restrict__ in, float* __restrict__ out) {
    const unsigned stride = NBLOCKS * NTHREADS;            // 303,104
    const size_t qsize = (size_t)512u * 256u * 256u;       // 33,554,432 elems per quadrant

    for (unsigned t = blockIdx.x * NTHREADS + threadIdx.x; t < NTILES; t += stride) {
        const unsigned tx = t & 63u;            // group of 4 output cols (0..63)
        const unsigned oy = (t >> 6) & 255u;    // output row (0..255)
        const unsigned p  = t >> 14;            // plane (0..511)

        // Input: rows 2*oy, 2*oy+1 of plane p; cols 8tx..8tx+7 (two float4 per row).
        const float4* __restrict__ in4 =
            reinterpret_cast<const float4*>(in) + ((size_t)p * 512u + 2u * oy) * 128u + 2u * tx;

        // Front-batched loads: 4 independent LDG.128 (MLP = 4).
        const float4 r0a = __ldcs(in4 + 0);
        const float4 r0b = __ldcs(in4 + 1);
        const float4 r1a = __ldcs(in4 + 128);
        const float4 r1b = __ldcs(in4 + 129);

        float4 ll, lh, hl, hh;
        {   // block 0: cols 8tx, 8tx+1
            const float a = r0a.x, b = r0a.y, c = r1a.x, d = r1a.y;
            ll.x = ( a + b + c + d) * 0.5f;  lh.x = (-a - b + c + d) * 0.5f;
            hl.x = (-a + b - c + d) * 0.5f;  hh.x = ( a - b - c + d) * 0.5f;
        }
        {   // block 1: cols 8tx+2, 8tx+3
            const float a = r0a.z, b = r0a.w, c = r1a.z, d = r1a.w;
            ll.y = ( a + b + c + d) * 0.5f;  lh.y = (-a - b + c + d) * 0.5f;
            hl.y = (-a + b - c + d) * 0.5f;  hh.y = ( a - b - c + d) * 0.5f;
        }
        {   // block 2: cols 8tx+4, 8tx+5
            const float a = r0b.x, b = r0b.y, c = r1b.x, d = r1b.y;
            ll.z = ( a + b + c + d) * 0.5f;  lh.z = (-a - b + c + d) * 0.5f;
            hl.z = (-a + b - c + d) * 0.5f;  hh.z = ( a - b - c + d) * 0.5f;
        }
        {   // block 3: cols 8tx+6, 8tx+7
            const float a = r0b.z, b = r0b.w, c = r1b.z, d = r1b.w;
            ll.w = ( a + b + c + d) * 0.5f;  lh.w = (-a - b + c + d) * 0.5f;
            hl.w = (-a + b - c + d) * 0.5f;  hh.w = ( a - b - c + d) * 0.5f;
        }

        // Output: element offset within a quadrant; multiple of 4 -> float4 aligned.
        const size_t obase = (((size_t)p * 256u + oy) * 256u) + 4u * tx;
        float* o0 = out + obase;
        __stcs(reinterpret_cast<float4*>(o0 + 0 * qsize), ll);
        __stcs(reinterpret_cast<float4*>(o0 + 1 * qsize), lh);
        __stcs(reinterpret_cast<float4*>(o0 + 2 * qsize), hl);
        __stcs(reinterpret_cast<float4*>(o0 + 3 * qsize), hh);
    }
}

extern "C" void kernel_launch(void* const* d_in, const int* in_sizes, int n_in,
                              void* d_out, int out_size) {
    const float* x = (const float*)d_in[0];
    float* out = (float*)d_out;
    haar_dwt_kernel<<<NBLOCKS, NTHREADS>>>(x, out);
}

// round 5
// speedup vs baseline: 1.1397x; 1.1397x over previous
#include <cuda_runtime.h>
#include <cstdint>

// Haar DWT level-1 on x: (8, 64, 512, 512) fp32 -> 4 quadrants (8,64,256,256)
// concatenated in d_out as [ll | lh | hl | hh].
//
// R2 shape (best measured DRAM%): per thread one 2x8 input patch (4x float4
// streaming loads, front-batched) -> four 2x2 Haar butterflies -> one float4
// streaming store per quadrant. Flat one-shot launch (persistent loop measured
// WORSE: per-warp MLP collapses across loop iterations). 512-thread blocks to
// halve CTA scheduling events; regs=32 keeps 64 warps/SM.
//
// planes P = 512, H = W = 512, outH = outW = 256
// total threads = 512 * 256 * 64 = 8,388,608 = 16384 blocks x 512

__global__ __launch_bounds__(512, 4)
void haar_dwt_kernel(const float* __restrict__ in, float* __restrict__ out) {
    const unsigned idx = blockIdx.x * 512u + threadIdx.x;   // < 8,388,608
    const unsigned tx = idx & 63u;             // group of 4 output cols (0..63)
    const unsigned oy = (idx >> 6) & 255u;     // output row (0..255)
    const unsigned p  = idx >> 14;             // plane (0..511)

    // Input: rows 2*oy and 2*oy+1 of plane p; cols 8tx..8tx+7 (two float4 each).
    const float4* __restrict__ in4 =
        reinterpret_cast<const float4*>(in) + ((size_t)p * 512u + 2u * oy) * 128u + 2u * tx;
    const float4 r0a = __ldcs(in4 + 0);      // row 2*oy,   cols 8tx..8tx+3
    const float4 r0b = __ldcs(in4 + 1);      // row 2*oy,   cols 8tx+4..8tx+7
    const float4 r1a = __ldcs(in4 + 128);    // row 2*oy+1, cols 8tx..8tx+3
    const float4 r1b = __ldcs(in4 + 129);    // row 2*oy+1, cols 8tx+4..8tx+7

    float4 ll, lh, hl, hh;

    {   // block 0: cols 8tx, 8tx+1
        const float a = r0a.x, b = r0a.y, c = r1a.x, d = r1a.y;
        ll.x = ( a + b + c + d) * 0.5f;  lh.x = (-a - b + c + d) * 0.5f;
        hl.x = (-a + b - c + d) * 0.5f;  hh.x = ( a - b - c + d) * 0.5f;
    }
    {   // block 1: cols 8tx+2, 8tx+3
        const float a = r0a.z, b = r0a.w, c = r1a.z, d = r1a.w;
        ll.y = ( a + b + c + d) * 0.5f;  lh.y = (-a - b + c + d) * 0.5f;
        hl.y = (-a + b - c + d) * 0.5f;  hh.y = ( a - b - c + d) * 0.5f;
    }
    {   // block 2: cols 8tx+4, 8tx+5
        const float a = r0b.x, b = r0b.y, c = r1b.x, d = r1b.y;
        ll.z = ( a + b + c + d) * 0.5f;  lh.z = (-a - b + c + d) * 0.5f;
        hl.z = (-a + b - c + d) * 0.5f;  hh.z = ( a - b - c + d) * 0.5f;
    }
    {   // block 3: cols 8tx+6, 8tx+7
        const float a = r0b.z, b = r0b.w, c = r1b.z, d = r1b.w;
        ll.w = ( a + b + c + d) * 0.5f;  lh.w = (-a - b + c + d) * 0.5f;
        hl.w = (-a + b - c + d) * 0.5f;  hh.w = ( a - b - c + d) * 0.5f;
    }

    // Output: element offset within a quadrant; multiple of 4 -> float4 aligned.
    const size_t qsize = (size_t)512u * 256u * 256u;               // 33,554,432
    const size_t obase = (((size_t)p * 256u + oy) * 256u) + 4u * tx;

    __stcs(reinterpret_cast<float4*>(out + 0 * qsize + obase), ll);
    __stcs(reinterpret_cast<float4*>(out + 1 * qsize + obase), lh);
    __stcs(reinterpret_cast<float4*>(out + 2 * qsize + obase), hl);
    __stcs(reinterpret_cast<float4*>(out + 3 * qsize + obase), hh);
}

extern "C" void kernel_launch(void* const* d_in, const int* in_sizes, int n_in,
                              void* d_out, int out_size) {
    const float* x = (const float*)d_in[0];
    float* out = (float*)d_out;
    haar_dwt_kernel<<<16384, 512>>>(x, out);
}